// round 5
// baseline (speedup 1.0000x reference)
#include <cuda_runtime.h>
#include <math.h>
#include <stddef.h>

// Problem constants
#define Bz    32
#define T     1024
#define F     256
#define Hh    256
#define C3    768      // 3 live gate chunks (i, f, g)
#define NB    128      // persistent blocks
#define HB    2        // H columns per block
#define NCOL  6        // HB * 3 chunks
#define NTH   256
#define OMEGA 32

// packed f32x2 helpers (Blackwell)
#define FFMA2(d, a, b) asm("fma.rn.f32x2 %0, %1, %2, %0;" : "+l"(d) : "l"(a), "l"(b))
#define UPK(v, lo, hi) asm("mov.b64 {%0, %1}, %2;" : "=f"(lo), "=f"(hi) : "l"(v))

// -------- device scratch (static; no cudaMalloc) --------
__device__ float        g_G[(size_t)T * C3 * Bz];   // [t][col][b] : x@W' cache, overwritten with Bm[t]=P2@a_cur_t
__device__ float        g_xrs[T];                   // sum_b P_r[b] * (x_t @ W_r)[b]
__device__ float        g_pubh[2][Bz * Hh];         // published h, [slot][b*256+k]
__device__ float        g_pubgp[2][NB];             // published gate partials per block
__device__ unsigned int g_flag[NB];                 // per-block monotonic step counter
__device__ float        g_hfin[Bz * Hh];            // final h for output

// ------------------------------------------------------------------
__global__ void init_kernel() {
    int tid = threadIdx.x;
    for (int i = tid; i < 2 * Bz * Hh; i += NTH) ((float*)g_pubh)[i] = 0.f;
    for (int i = tid; i < 2 * NB; i += NTH) ((float*)g_pubgp)[i] = 0.f;
    if (tid < NB) g_flag[tid] = 0u;
}

// g_xrs[t] = sum_b P_r[b] * sum_f x[b,t,f] * W_r[f]
__global__ __launch_bounds__(256) void xr_kernel(const float* __restrict__ x,
                                                 const float* __restrict__ W_r,
                                                 const float* __restrict__ P_r) {
    __shared__ float xs[32];
    int t = blockIdx.x;
    int tid = threadIdx.x;
    int b = tid >> 3, ks = tid & 7;
    const float4* xv = (const float4*)(x + ((size_t)b * T + t) * F);
    const float4* wr = (const float4*)W_r;
    float s = 0.f;
#pragma unroll
    for (int q = 0; q < 8; q++) {
        float4 a = xv[ks * 8 + q];
        float4 w = wr[ks * 8 + q];
        s += a.x * w.x + a.y * w.y + a.z * w.z + a.w * w.w;
    }
    s += __shfl_xor_sync(0xffffffffu, s, 1);
    s += __shfl_xor_sync(0xffffffffu, s, 2);
    s += __shfl_xor_sync(0xffffffffu, s, 4);
    if (ks == 0) xs[b] = s * P_r[b];
    __syncthreads();
    if (tid < 32) {
        float v = xs[tid];
#pragma unroll
        for (int o = 16; o; o >>= 1) v += __shfl_xor_sync(0xffffffffu, v, o);
        if (tid == 0) g_xrs[t] = v;
    }
}

// G[t][col][b] = sum_f x[b,t,f] * W[f,col], col < 768. Grid: (12 col-tiles, 1024 t).
__global__ __launch_bounds__(256) void gemm_kernel(const float* __restrict__ x,
                                                   const float* __restrict__ W) {
    __shared__ float xsh[Bz][33];
    __shared__ float wsh[32][64];
    int t = blockIdx.y;
    int colbase = blockIdx.x * 64;
    int tid = threadIdx.x;
    int b = tid & 31, cg = tid >> 5;
    unsigned long long acc[4] = {0ull, 0ull, 0ull, 0ull};

    for (int kt = 0; kt < 8; kt++) {
        int k0 = kt * 32;
        __syncthreads();
        {
            int lb = tid >> 3, kq = tid & 7;
            float4 v = *(const float4*)(x + ((size_t)lb * T + t) * F + k0 + kq * 4);
            xsh[lb][kq * 4 + 0] = v.x; xsh[lb][kq * 4 + 1] = v.y;
            xsh[lb][kq * 4 + 2] = v.z; xsh[lb][kq * 4 + 3] = v.w;
            int kk = tid >> 3, c4 = (tid & 7) * 8;
            const float* wrow = W + (size_t)(k0 + kk) * 1024 + colbase + c4;
            *(float4*)&wsh[kk][c4] = *(const float4*)(wrow);
            *(float4*)&wsh[kk][c4 + 4] = *(const float4*)(wrow + 4);
        }
        __syncthreads();
#pragma unroll
        for (int kk = 0; kk < 32; kk++) {
            unsigned xu = __float_as_uint(xsh[b][kk]);
            unsigned long long xx;
            asm("mov.b64 %0, {%1, %1};" : "=l"(xx) : "r"(xu));
            const longlong2* wp = (const longlong2*)&wsh[kk][cg * 8];
            longlong2 w0 = wp[0], w1 = wp[1];
            FFMA2(acc[0], xx, w0.x); FFMA2(acc[1], xx, w0.y);
            FFMA2(acc[2], xx, w1.x); FFMA2(acc[3], xx, w1.y);
        }
    }
    size_t base = (size_t)t * (C3 * Bz) + (size_t)(colbase + cg * 8) * Bz + b;
#pragma unroll
    for (int i = 0; i < 4; i++) {
        float lo, hi; UPK(acc[i], lo, hi);
        g_G[base + (size_t)(2 * i) * Bz] = lo;
        g_G[base + (size_t)(2 * i + 1) * Bz] = hi;
    }
}

// ------------------------------------------------------------------
struct __align__(16) RecSmem {
    float hs[Bz][260];      // h, padded rows (stride 260 -> conflict-free .128)
    float Ush[NCOL][260];   // 6 U' columns, k-contiguous
    float Psh[Bz][68];      // P [32][64] padded
    float pp[8][NCOL][Bz];  // per-warp K-split partials of h@U'
    float gsh[NCOL][Bz];    // G[t] slice
    float ac[NCOL][Bz];     // a_cur slice
    float gt[NCOL][Bz];     // gates slice
    float gpsh[NB];         // gate partials from all blocks
    float Prsh[Bz];
    float biassh[NCOL];
    float s_gpp[2];
    int   s_idx;
};

__global__ __launch_bounds__(NTH, 1) void rec_kernel(
    const float* __restrict__ U, const float* __restrict__ P,
    const float* __restrict__ B_bias, const float* __restrict__ P_r,
    const float* __restrict__ U_r, const float* __restrict__ W_out,
    const float* __restrict__ b_out, float* __restrict__ out)
{
    extern __shared__ char smem_raw[];
    RecSmem& S = *reinterpret_cast<RecSmem*>(smem_raw);
    const int tid = threadIdx.x;
    const int w = tid >> 5, lane = tid & 31;
    const int bid = blockIdx.x;
    const int j0 = bid * HB;

    // ---- one-time preloads ----
    for (int i = tid; i < NCOL * Hh; i += NTH) {
        int cl = i >> 8, k = i & 255;
        int colg = (cl >> 1) * Hh + j0 + (cl & 1);
        S.Ush[cl][k] = U[(size_t)k * 1024 + colg];
    }
    for (int i = tid; i < Bz * 64; i += NTH) S.Psh[i >> 6][i & 63] = P[i];
    if (tid < Bz) S.Prsh[tid] = P_r[tid];
    if (tid < NCOL) {
        int colg = (tid >> 1) * Hh + j0 + (tid & 1);
        S.biassh[tid] = B_bias[colg];
    }
    // per-thread constants
    const int mycl = w;                                    // for tid<192 stages
    const int mycolg = (mycl >> 1) * Hh + j0 + (mycl & 1); // valid when tid<192
    float urj = (tid < 64) ? U_r[j0 + w] : 0.f;            // w = jl for tid<64
    float c_reg = 0.f;                                     // c state for (jl=w, b=lane), tid<64
    __syncthreads();

    for (int t = 0; t < T; t++) {
        const int slot_in = (t - 1) & 1;   // published at step t-1
        // ---- S1: poll per-block flags (distinct addresses), fetch gate partials ----
        if (tid < NB) {
            if (t > 0) {
                unsigned v;
                do {
                    asm volatile("ld.global.acquire.gpu.u32 %0, [%1];"
                                 : "=r"(v) : "l"(&g_flag[tid]) : "memory");
                } while (v < (unsigned)t);
            }
            S.gpsh[tid] = g_pubgp[slot_in][tid];
        }
        __syncthreads();

        // ---- S2: warp0 computes gate+idx; warps 1-7 load h (8KB, L2-fresh) ----
        if (w == 0) {
            float v = S.gpsh[lane] + S.gpsh[lane + 32] + S.gpsh[lane + 64] + S.gpsh[lane + 96];
#pragma unroll
            for (int o = 16; o; o >>= 1) v += __shfl_xor_sync(0xffffffffu, v, o);
            if (lane == 0) {
                v += g_xrs[t];
                float gate = 1.f / (1.f + expf(-v));
                int hi = (t - 1) > 0 ? (t - 1) : 0;
                int idx = (int)rintf((float)t * gate);
                idx = idx < 0 ? 0 : (idx > hi ? hi : idx);
                S.s_idx = idx;
            }
            // G[t] slice (192 floats)
            const float* gsrc = &g_G[(size_t)t * (C3 * Bz)];
            for (int q = lane; q < 48; q += 32) {
                int cl = q >> 3, qq = q & 7;
                int colg = (cl >> 1) * Hh + j0 + (cl & 1);
                *(float4*)&S.gsh[cl][qq * 4] = *(const float4*)&gsrc[(size_t)colg * Bz + qq * 4];
            }
        } else {
            const float4* hb = (const float4*)g_pubh[slot_in];
            for (int q = tid - 32; q < 2048; q += 224) {
                int b = q >> 6, kq = q & 63;
                ((float4*)&S.hs[b][0])[kq] = __ldcg(&hb[q]);
            }
        }
        __syncthreads();

        // ---- S3: prefetch recall term, then matvec h@U' (packed f32x2) ----
        const bool rec = (t >= OMEGA);
        const int sidx = S.s_idx;
        float bmv = 0.f;
        if (rec && tid < 192)
            bmv = __ldg(&g_G[(size_t)sidx * (C3 * Bz) + (size_t)mycolg * Bz + lane]);
        {
            unsigned long long acc[NCOL] = {0ull, 0ull, 0ull, 0ull, 0ull, 0ull};
            const longlong2* hrow = (const longlong2*)&S.hs[lane][0];
#pragma unroll
            for (int q = 0; q < 8; q++) {
                longlong2 hq = hrow[w * 8 + q];
#pragma unroll
                for (int cl = 0; cl < NCOL; cl++) {
                    longlong2 uq = ((const longlong2*)&S.Ush[cl][0])[w * 8 + q];
                    FFMA2(acc[cl], hq.x, uq.x);
                    FFMA2(acc[cl], hq.y, uq.y);
                }
            }
#pragma unroll
            for (int cl = 0; cl < NCOL; cl++) {
                float lo, hi; UPK(acc[cl], lo, hi);
                S.pp[w][cl][lane] = lo + hi;
            }
        }
        __syncthreads();

        // ---- S4a: reduce K-split partials -> a_cur slice ----
        if (tid < 192) {
            float s = S.gsh[mycl][lane];
#pragma unroll
            for (int ww = 0; ww < 8; ww++) s += S.pp[ww][mycl][lane];
            S.ac[mycl][lane] = s;
        }
        __syncthreads();

        // ---- S4b: P-mix (y1 = P1@ac, y2 = P2@ac); store Bm[t]=y2; gates ----
        if (tid < 192) {
            unsigned long long a1 = 0ull, a2 = 0ull;
            const longlong2* prow1 = (const longlong2*)&S.Psh[lane][0];
            const longlong2* prow2 = (const longlong2*)&S.Psh[lane][32];
            const longlong2* arow  = (const longlong2*)&S.ac[mycl][0];
#pragma unroll
            for (int q = 0; q < 8; q++) {
                longlong2 av = arow[q];
                longlong2 p1 = prow1[q];
                FFMA2(a1, p1.x, av.x); FFMA2(a1, p1.y, av.y);
                longlong2 p2 = prow2[q];
                FFMA2(a2, p2.x, av.x); FFMA2(a2, p2.y, av.y);
            }
            float l1, h1, l2, h2;
            UPK(a1, l1, h1); UPK(a2, l2, h2);
            float y1 = l1 + h1, y2 = l2 + h2;
            g_G[(size_t)t * (C3 * Bz) + (size_t)mycolg * Bz + lane] = y2;
            S.gt[mycl][lane] = S.biassh[mycl] + y1 + (rec ? bmv : y2);
        }
        __syncthreads();

        // ---- S5: activations, state update, publish ----
        if (tid < 64) {
            float gi = S.gt[w][lane], gf = S.gt[2 + w][lane], gg = S.gt[4 + w][lane];
            float iv = 1.f / (1.f + expf(-gi));
            float fv = 1.f / (1.f + expf(-gf));
            float gv = tanhf(gg);
            c_reg = fv * c_reg + iv * gv;
            float h = iv * tanhf(c_reg);   // o_t = i_t (faithful to source)
            g_pubh[t & 1][lane * Hh + j0 + w] = h;
            if (t == T - 1) g_hfin[lane * Hh + j0 + w] = h;
            float v = S.Prsh[lane] * h * urj;
#pragma unroll
            for (int o = 16; o; o >>= 1) v += __shfl_xor_sync(0xffffffffu, v, o);
            if (lane == 0) S.s_gpp[w] = v;
            asm volatile("bar.sync 1, 64;");
            if (tid == 0) {
                g_pubgp[t & 1][bid] = S.s_gpp[0] + S.s_gpp[1];
                __threadfence();
                asm volatile("st.global.relaxed.gpu.u32 [%0], %1;"
                             :: "l"(&g_flag[bid]), "r"((unsigned)(t + 1)) : "memory");
            }
        }
        // no trailing sync: next S1's __syncthreads orders everything
    }

    // ---- final: out = h_final @ W_out + b_out (block 0) ----
    if (bid == 0) {
        if (tid < NB) {
            unsigned v;
            do {
                asm volatile("ld.global.acquire.gpu.u32 %0, [%1];"
                             : "=r"(v) : "l"(&g_flag[tid]) : "memory");
            } while (v < (unsigned)T);
        }
        __syncthreads();
        int b = tid >> 3, ks = tid & 7;
        const float4* hr4 = (const float4*)(g_hfin + b * Hh);
        const float4* wo4 = (const float4*)W_out;
        float s = 0.f;
#pragma unroll
        for (int q = 0; q < 8; q++) {
            float4 hv = __ldcg(&hr4[ks * 8 + q]);
            float4 wv = wo4[ks * 8 + q];
            s += hv.x * wv.x + hv.y * wv.y + hv.z * wv.z + hv.w * wv.w;
        }
        s += __shfl_xor_sync(0xffffffffu, s, 1);
        s += __shfl_xor_sync(0xffffffffu, s, 2);
        s += __shfl_xor_sync(0xffffffffu, s, 4);
        if (ks == 0) out[b] = s + b_out[0];
    }
}

// ------------------------------------------------------------------
extern "C" void kernel_launch(void* const* d_in, const int* in_sizes, int n_in,
                              void* d_out, int out_size) {
    const float* x      = (const float*)d_in[0];   // [32,1024,256]
    const float* W      = (const float*)d_in[1];   // [256,1024]
    const float* U      = (const float*)d_in[2];   // [256,1024]
    const float* P      = (const float*)d_in[3];   // [32,64]
    const float* B_bias = (const float*)d_in[4];   // [1024]
    const float* W_r    = (const float*)d_in[5];   // [256,1]
    const float* P_r    = (const float*)d_in[6];   // [1,32]
    const float* U_r    = (const float*)d_in[7];   // [256,1]
    const float* W_out  = (const float*)d_in[8];   // [256,1]
    const float* b_out  = (const float*)d_in[9];   // [1]
    float* out = (float*)d_out;                    // [32,1]

    (void)in_sizes; (void)n_in; (void)out_size;

    init_kernel<<<1, NTH>>>();
    xr_kernel<<<T, 256>>>(x, W_r, P_r);
    gemm_kernel<<<dim3(12, T), 256>>>(x, W);

    cudaFuncSetAttribute(rec_kernel, cudaFuncAttributeMaxDynamicSharedMemorySize,
                         (int)sizeof(RecSmem));
    rec_kernel<<<NB, NTH, sizeof(RecSmem)>>>(U, P, B_bias, P_r, U_r, W_out, b_out, out);
}

// round 6
// speedup vs baseline: 1.5424x; 1.5424x over previous
#include <cuda_runtime.h>
#include <math.h>
#include <stddef.h>

// Problem constants
#define Bz    32
#define T     1024
#define F     256
#define Hh    256
#define C3    768      // 3 live gate chunks (i, f, g)
#define NB    128      // persistent blocks
#define HB    2        // H columns per block
#define NCOL  6        // HB * 3 chunks
#define NTH   256
#define OMEGA 32

// packed f32x2 helpers (Blackwell)
#define FFMA2(d, a, b) asm("fma.rn.f32x2 %0, %1, %2, %0;" : "+l"(d) : "l"(a), "l"(b))
#define UPK(v, lo, hi) asm("mov.b64 {%0, %1}, %2;" : "=f"(lo), "=f"(hi) : "l"(v))

// -------- device scratch (static; no cudaMalloc) --------
__device__ float g_G[(size_t)T * C3 * Bz];   // [t][col][b]: x@W' cache, overwritten with Bm[t]=P2@a_cur_t
__device__ float g_xrs[T];                   // sum_b P_r[b] * (x_t @ W_r)[b]
__device__ float g_pubh[2][Bz * Hh];         // published h, [slot][b*256+k]
__device__ uint2 g_sync[2][NB][16];          // one 128B line per block: [0] = {flag, payload}
__device__ float g_hfin[Bz * Hh];            // final h for output

// ------------------------------------------------------------------
__global__ void init_kernel() {
    int tid = threadIdx.x;
    for (int i = tid; i < 2 * Bz * Hh; i += NTH) ((float*)g_pubh)[i] = 0.f;
    uint2* s = (uint2*)g_sync;
    for (int i = tid; i < 2 * NB * 16; i += NTH) s[i] = make_uint2(0u, 0u);
}

// g_xrs[t] = sum_b P_r[b] * sum_f x[b,t,f] * W_r[f]
__global__ __launch_bounds__(256) void xr_kernel(const float* __restrict__ x,
                                                 const float* __restrict__ W_r,
                                                 const float* __restrict__ P_r) {
    __shared__ float xs[32];
    int t = blockIdx.x;
    int tid = threadIdx.x;
    int b = tid >> 3, ks = tid & 7;
    const float4* xv = (const float4*)(x + ((size_t)b * T + t) * F);
    const float4* wr = (const float4*)W_r;
    float s = 0.f;
#pragma unroll
    for (int q = 0; q < 8; q++) {
        float4 a = xv[ks * 8 + q];
        float4 w = wr[ks * 8 + q];
        s += a.x * w.x + a.y * w.y + a.z * w.z + a.w * w.w;
    }
    s += __shfl_xor_sync(0xffffffffu, s, 1);
    s += __shfl_xor_sync(0xffffffffu, s, 2);
    s += __shfl_xor_sync(0xffffffffu, s, 4);
    if (ks == 0) xs[b] = s * P_r[b];
    __syncthreads();
    if (tid < 32) {
        float v = xs[tid];
#pragma unroll
        for (int o = 16; o; o >>= 1) v += __shfl_xor_sync(0xffffffffu, v, o);
        if (tid == 0) g_xrs[t] = v;
    }
}

// G[t][col][b] = sum_f x[b,t,f] * W[f,col], col < 768. Grid: (12 col-tiles, 1024 t).
__global__ __launch_bounds__(256) void gemm_kernel(const float* __restrict__ x,
                                                   const float* __restrict__ W) {
    __shared__ float xsh[Bz][33];
    __shared__ float wsh[32][64];
    int t = blockIdx.y;
    int colbase = blockIdx.x * 64;
    int tid = threadIdx.x;
    int b = tid & 31, cg = tid >> 5;
    unsigned long long acc[4] = {0ull, 0ull, 0ull, 0ull};

    for (int kt = 0; kt < 8; kt++) {
        int k0 = kt * 32;
        __syncthreads();
        {
            int lb = tid >> 3, kq = tid & 7;
            float4 v = *(const float4*)(x + ((size_t)lb * T + t) * F + k0 + kq * 4);
            xsh[lb][kq * 4 + 0] = v.x; xsh[lb][kq * 4 + 1] = v.y;
            xsh[lb][kq * 4 + 2] = v.z; xsh[lb][kq * 4 + 3] = v.w;
            int kk = tid >> 3, c4 = (tid & 7) * 8;
            const float* wrow = W + (size_t)(k0 + kk) * 1024 + colbase + c4;
            *(float4*)&wsh[kk][c4] = *(const float4*)(wrow);
            *(float4*)&wsh[kk][c4 + 4] = *(const float4*)(wrow + 4);
        }
        __syncthreads();
#pragma unroll
        for (int kk = 0; kk < 32; kk++) {
            unsigned xu = __float_as_uint(xsh[b][kk]);
            unsigned long long xx;
            asm("mov.b64 %0, {%1, %1};" : "=l"(xx) : "r"(xu));
            const longlong2* wp = (const longlong2*)&wsh[kk][cg * 8];
            longlong2 w0 = wp[0], w1 = wp[1];
            FFMA2(acc[0], xx, w0.x); FFMA2(acc[1], xx, w0.y);
            FFMA2(acc[2], xx, w1.x); FFMA2(acc[3], xx, w1.y);
        }
    }
    size_t base = (size_t)t * (C3 * Bz) + (size_t)(colbase + cg * 8) * Bz + b;
#pragma unroll
    for (int i = 0; i < 4; i++) {
        float lo, hi; UPK(acc[i], lo, hi);
        g_G[base + (size_t)(2 * i) * Bz] = lo;
        g_G[base + (size_t)(2 * i + 1) * Bz] = hi;
    }
}

// ------------------------------------------------------------------
struct __align__(16) RecSmem {
    float hs[Bz][260];      // h, padded rows (stride 260 -> conflict-free .128)
    float Ush[NCOL][260];   // 6 U' columns, k-contiguous
    float Psh[Bz][68];      // P [32][64] padded (stride 17 quads -> conflict-free .128)
    float pp[8][NCOL][Bz];  // per-warp K-split partials of h@U'
    float gsh[NCOL][Bz];    // G[t] slice (x@W')
    float ac[NCOL][Bz];     // a_cur slice
    float gt[NCOL][Bz];     // gates slice
    float Prsh[Bz];
    float biassh[NCOL];
    float s_gpp[2];
    int   s_idx;
};

__global__ __launch_bounds__(NTH, 1) void rec_kernel(
    const float* __restrict__ U, const float* __restrict__ P,
    const float* __restrict__ B_bias, const float* __restrict__ P_r,
    const float* __restrict__ U_r, const float* __restrict__ W_out,
    const float* __restrict__ b_out, float* __restrict__ out)
{
    extern __shared__ char smem_raw[];
    RecSmem& S = *reinterpret_cast<RecSmem*>(smem_raw);
    const int tid = threadIdx.x;
    const int w = tid >> 5, lane = tid & 31;
    const int bid = blockIdx.x;
    const int j0 = bid * HB;

    // ---- one-time preloads ----
    for (int i = tid; i < NCOL * Hh; i += NTH) {
        int cl = i >> 8, k = i & 255;
        int colg = (cl >> 1) * Hh + j0 + (cl & 1);
        S.Ush[cl][k] = U[(size_t)k * 1024 + colg];
    }
    for (int i = tid; i < Bz * 64; i += NTH) S.Psh[i >> 6][i & 63] = P[i];
    if (tid < Bz) S.Prsh[tid] = P_r[tid];
    if (tid < NCOL) {
        int colg = (tid >> 1) * Hh + j0 + (tid & 1);
        S.biassh[tid] = B_bias[colg];
    }
    const int mycl = w;                                    // valid for tid<192 stages
    const int mycolg = (mycl >> 1) * Hh + j0 + (mycl & 1);
    float urj = (tid < 64) ? U_r[j0 + w] : 0.f;            // w = jl for tid<64
    float c_reg = 0.f;                                     // c state for (jl=w, b=lane), tid<64
    __syncthreads();

    for (int t = 0; t < T; t++) {
        const int slot = (t - 1) & 1;   // slot published at step t-1 (t=0: both zeroed)

        // ---- S1: warp0 polls 128 line-strided {flag,payload} slots; gate + idx ----
        if (w == 0) {
            float psum = 0.f;
            if (t > 0) {
#pragma unroll
                for (int i = 0; i < 4; i++) {
                    const uint2* ap = &g_sync[slot][lane + 32 * i][0];
                    unsigned fl, pv;
                    do {
                        asm volatile("ld.global.acquire.gpu.v2.u32 {%0,%1}, [%2];"
                                     : "=r"(fl), "=r"(pv) : "l"(ap) : "memory");
                    } while (fl < (unsigned)t);
                    psum += __uint_as_float(pv);
                }
            }
#pragma unroll
            for (int o = 16; o; o >>= 1) psum += __shfl_xor_sync(0xffffffffu, psum, o);
            if (lane == 0) {
                float v = psum + g_xrs[t];
                float gate = 1.f / (1.f + expf(-v));
                int hi = (t - 1) > 0 ? (t - 1) : 0;
                int idx = (int)rintf((float)t * gate);
                idx = idx < 0 ? 0 : (idx > hi ? hi : idx);
                S.s_idx = idx;
            }
        }
        __syncthreads();

        // ---- S2: all 256 threads load h (32KB, L2-fresh); tid<48 load G[t] slice ----
        {
            const float4* hb = (const float4*)g_pubh[slot];
#pragma unroll
            for (int r = 0; r < 8; r++) {
                int q = tid + r * NTH;
                ((float4*)&S.hs[q >> 6][0])[q & 63] = __ldcg(&hb[q]);
            }
            if (tid < 48) {
                int cl = tid >> 3, qq = tid & 7;
                int colg = (cl >> 1) * Hh + j0 + (cl & 1);
                *(float4*)&S.gsh[cl][qq * 4] =
                    *(const float4*)&g_G[(size_t)t * (C3 * Bz) + (size_t)colg * Bz + qq * 4];
            }
        }
        __syncthreads();

        // ---- S3: prefetch recall term (Bm[sidx]), then matvec h@U' (f32x2) ----
        const bool rec = (t >= OMEGA);
        const int sidx = S.s_idx;
        float bmv = 0.f;
        if (rec && tid < 192)
            bmv = __ldcg(&g_G[(size_t)sidx * (C3 * Bz) + (size_t)mycolg * Bz + lane]);
        {
            unsigned long long acc[NCOL] = {0ull, 0ull, 0ull, 0ull, 0ull, 0ull};
            const longlong2* hrow = (const longlong2*)&S.hs[lane][0];
#pragma unroll
            for (int q = 0; q < 8; q++) {
                longlong2 hq = hrow[w * 8 + q];
#pragma unroll
                for (int cl = 0; cl < NCOL; cl++) {
                    longlong2 uq = ((const longlong2*)&S.Ush[cl][0])[w * 8 + q];  // broadcast
                    FFMA2(acc[cl], hq.x, uq.x);
                    FFMA2(acc[cl], hq.y, uq.y);
                }
            }
#pragma unroll
            for (int cl = 0; cl < NCOL; cl++) {
                float lo, hi; UPK(acc[cl], lo, hi);
                S.pp[w][cl][lane] = lo + hi;
            }
        }
        __syncthreads();

        // ---- S4a: reduce K-split partials -> a_cur slice ----
        if (tid < 192) {
            float s = S.gsh[mycl][lane];
#pragma unroll
            for (int ww = 0; ww < 8; ww++) s += S.pp[ww][mycl][lane];
            S.ac[mycl][lane] = s;
        }
        __syncthreads();

        // ---- S4b: P-mix (y1 = P1@ac, y2 = P2@ac); store Bm[t]=y2; gates ----
        if (tid < 192) {
            unsigned long long a1 = 0ull, a2 = 0ull;
            const longlong2* prow1 = (const longlong2*)&S.Psh[lane][0];
            const longlong2* prow2 = (const longlong2*)&S.Psh[lane][32];
            const longlong2* arow  = (const longlong2*)&S.ac[mycl][0];   // broadcast
#pragma unroll
            for (int q = 0; q < 8; q++) {
                longlong2 av = arow[q];
                longlong2 p1 = prow1[q];
                FFMA2(a1, p1.x, av.x); FFMA2(a1, p1.y, av.y);
                longlong2 p2 = prow2[q];
                FFMA2(a2, p2.x, av.x); FFMA2(a2, p2.y, av.y);
            }
            float l1, h1, l2, h2;
            UPK(a1, l1, h1); UPK(a2, l2, h2);
            float y1 = l1 + h1, y2 = l2 + h2;
            g_G[(size_t)t * (C3 * Bz) + (size_t)mycolg * Bz + lane] = y2;  // Bm[t]
            S.gt[mycl][lane] = S.biassh[mycl] + y1 + (rec ? bmv : y2);
        }
        __syncthreads();

        // ---- S5: activations, state update, publish {h, gate partial, flag} ----
        if (tid < 64) {
            float gi = S.gt[w][lane], gf = S.gt[2 + w][lane], gg = S.gt[4 + w][lane];
            float iv = 1.f / (1.f + expf(-gi));
            float fv = 1.f / (1.f + expf(-gf));
            float gv = tanhf(gg);
            c_reg = fv * c_reg + iv * gv;
            float h = iv * tanhf(c_reg);   // o_t = i_t (faithful to source)
            g_pubh[t & 1][lane * Hh + j0 + w] = h;
            if (t == T - 1) g_hfin[lane * Hh + j0 + w] = h;
            float v = S.Prsh[lane] * h * urj;
#pragma unroll
            for (int o = 16; o; o >>= 1) v += __shfl_xor_sync(0xffffffffu, v, o);
            if (lane == 0) S.s_gpp[w] = v;
            asm volatile("bar.sync 1, 64;");
            if (tid == 0) {
                float p = S.s_gpp[0] + S.s_gpp[1];
                __threadfence();
                asm volatile("st.global.relaxed.gpu.v2.u32 [%0], {%1,%2};"
                             :: "l"(&g_sync[t & 1][bid][0]),
                                "r"((unsigned)(t + 1)), "r"(__float_as_uint(p))
                             : "memory");
            }
        }
        // no trailing sync: next S1's __syncthreads orders shared-memory reuse
    }

    // ---- final: out = h_final @ W_out + b_out (block 0) ----
    if (bid == 0) {
        if (tid < NB) {
            const uint2* ap = &g_sync[(T - 1) & 1][tid][0];
            unsigned fl, pv;
            do {
                asm volatile("ld.global.acquire.gpu.v2.u32 {%0,%1}, [%2];"
                             : "=r"(fl), "=r"(pv) : "l"(ap) : "memory");
            } while (fl < (unsigned)T);
        }
        __syncthreads();
        int b = tid >> 3, ks = tid & 7;
        const float4* hr4 = (const float4*)(g_hfin + b * Hh);
        const float4* wo4 = (const float4*)W_out;
        float s = 0.f;
#pragma unroll
        for (int q = 0; q < 8; q++) {
            float4 hv = __ldcg(&hr4[ks * 8 + q]);
            float4 wv = wo4[ks * 8 + q];
            s += hv.x * wv.x + hv.y * wv.y + hv.z * wv.z + hv.w * wv.w;
        }
        s += __shfl_xor_sync(0xffffffffu, s, 1);
        s += __shfl_xor_sync(0xffffffffu, s, 2);
        s += __shfl_xor_sync(0xffffffffu, s, 4);
        if (ks == 0) out[b] = s + b_out[0];
    }
}

// ------------------------------------------------------------------
extern "C" void kernel_launch(void* const* d_in, const int* in_sizes, int n_in,
                              void* d_out, int out_size) {
    const float* x      = (const float*)d_in[0];   // [32,1024,256]
    const float* W      = (const float*)d_in[1];   // [256,1024]
    const float* U      = (const float*)d_in[2];   // [256,1024]
    const float* P      = (const float*)d_in[3];   // [32,64]
    const float* B_bias = (const float*)d_in[4];   // [1024]
    const float* W_r    = (const float*)d_in[5];   // [256,1]
    const float* P_r    = (const float*)d_in[6];   // [1,32]
    const float* U_r    = (const float*)d_in[7];   // [256,1]
    const float* W_out  = (const float*)d_in[8];   // [256,1]
    const float* b_out  = (const float*)d_in[9];   // [1]
    float* out = (float*)d_out;                    // [32,1]

    (void)in_sizes; (void)n_in; (void)out_size;

    init_kernel<<<1, NTH>>>();
    xr_kernel<<<T, 256>>>(x, W_r, P_r);
    gemm_kernel<<<dim3(12, T), 256>>>(x, W);

    cudaFuncSetAttribute(rec_kernel, cudaFuncAttributeMaxDynamicSharedMemorySize,
                         (int)sizeof(RecSmem));
    rec_kernel<<<NB, NTH, sizeof(RecSmem)>>>(U, P, B_bias, P_r, U_r, W_out, b_out, out);
}

// round 8
// speedup vs baseline: 2.0393x; 1.3222x over previous
#include <cuda_runtime.h>
#include <math.h>
#include <stddef.h>

// Problem constants
#define Bz    32
#define T     1024
#define F     256
#define Hh    256
#define C3    768      // 3 live gate chunks (i, f, g)
#define NB    128      // persistent blocks
#define HB    2        // H columns per block
#define NCOL  6        // HB * 3 chunks
#define NTH   256
#define OMEGA 32

// packed f32x2 helpers (Blackwell)
#define FFMA2(d, a, b) asm("fma.rn.f32x2 %0, %1, %2, %0;" : "+l"(d) : "l"(a), "l"(b))
#define UPK(v, lo, hi) asm("mov.b64 {%0, %1}, %2;" : "=f"(lo), "=f"(hi) : "l"(v))

// -------- device scratch (static; no cudaMalloc) --------
__device__ float g_G[(size_t)T * C3 * Bz];   // [t][col][b]: x@W' cache -> overwritten with Bm[t]=P2@a_cur_t (block-private columns!)
__device__ float g_xrs[T];                   // sum_b P_r[b] * (x_t @ W_r)[b]
__device__ float g_pubh[2][Bz * Hh];         // published h, [slot][b*256+k]
__device__ uint2 g_sync[2][NB][16];          // one 128B line per block: [0] = {flag, gate-partial}
__device__ float g_hfin[Bz * Hh];            // final h for output

// ------------------------------------------------------------------
__global__ void init_kernel() {
    int tid = threadIdx.x;
    for (int i = tid; i < 2 * Bz * Hh; i += NTH) ((float*)g_pubh)[i] = 0.f;
    uint2* s = (uint2*)g_sync;
    for (int i = tid; i < 2 * NB * 16; i += NTH) s[i] = make_uint2(0u, 0u);
}

// g_xrs[t] = sum_b P_r[b] * sum_f x[b,t,f] * W_r[f]
__global__ __launch_bounds__(256) void xr_kernel(const float* __restrict__ x,
                                                 const float* __restrict__ W_r,
                                                 const float* __restrict__ P_r) {
    __shared__ float xs[32];
    int t = blockIdx.x;
    int tid = threadIdx.x;
    int b = tid >> 3, ks = tid & 7;
    const float4* xv = (const float4*)(x + ((size_t)b * T + t) * F);
    const float4* wr = (const float4*)W_r;
    float s = 0.f;
#pragma unroll
    for (int q = 0; q < 8; q++) {
        float4 a = xv[ks * 8 + q];
        float4 w = wr[ks * 8 + q];
        s += a.x * w.x + a.y * w.y + a.z * w.z + a.w * w.w;
    }
    s += __shfl_xor_sync(0xffffffffu, s, 1);
    s += __shfl_xor_sync(0xffffffffu, s, 2);
    s += __shfl_xor_sync(0xffffffffu, s, 4);
    if (ks == 0) xs[b] = s * P_r[b];
    __syncthreads();
    if (tid < 32) {
        float v = xs[tid];
#pragma unroll
        for (int o = 16; o; o >>= 1) v += __shfl_xor_sync(0xffffffffu, v, o);
        if (tid == 0) g_xrs[t] = v;
    }
}

// G[t][col][b] = sum_f x[b,t,f] * W[f,col], col < 768. Grid: (12 col-tiles, 1024 t).
__global__ __launch_bounds__(256) void gemm_kernel(const float* __restrict__ x,
                                                   const float* __restrict__ W) {
    __shared__ float xsh[Bz][33];
    __shared__ float wsh[32][64];
    int t = blockIdx.y;
    int colbase = blockIdx.x * 64;
    int tid = threadIdx.x;
    int b = tid & 31, cg = tid >> 5;
    unsigned long long acc[4] = {0ull, 0ull, 0ull, 0ull};

    for (int kt = 0; kt < 8; kt++) {
        int k0 = kt * 32;
        __syncthreads();
        {
            int lb = tid >> 3, kq = tid & 7;
            float4 v = *(const float4*)(x + ((size_t)lb * T + t) * F + k0 + kq * 4);
            xsh[lb][kq * 4 + 0] = v.x; xsh[lb][kq * 4 + 1] = v.y;
            xsh[lb][kq * 4 + 2] = v.z; xsh[lb][kq * 4 + 3] = v.w;
            int kk = tid >> 3, c4 = (tid & 7) * 8;
            const float* wrow = W + (size_t)(k0 + kk) * 1024 + colbase + c4;
            *(float4*)&wsh[kk][c4] = *(const float4*)(wrow);
            *(float4*)&wsh[kk][c4 + 4] = *(const float4*)(wrow + 4);
        }
        __syncthreads();
#pragma unroll
        for (int kk = 0; kk < 32; kk++) {
            unsigned xu = __float_as_uint(xsh[b][kk]);
            unsigned long long xx;
            asm("mov.b64 %0, {%1, %1};" : "=l"(xx) : "r"(xu));
            const longlong2* wp = (const longlong2*)&wsh[kk][cg * 8];
            longlong2 w0 = wp[0], w1 = wp[1];
            FFMA2(acc[0], xx, w0.x); FFMA2(acc[1], xx, w0.y);
            FFMA2(acc[2], xx, w1.x); FFMA2(acc[3], xx, w1.y);
        }
    }
    size_t base = (size_t)t * (C3 * Bz) + (size_t)(colbase + cg * 8) * Bz + b;
#pragma unroll
    for (int i = 0; i < 4; i++) {
        float lo, hi; UPK(acc[i], lo, hi);
        g_G[base + (size_t)(2 * i) * Bz] = lo;
        g_G[base + (size_t)(2 * i + 1) * Bz] = hi;
    }
}

// ------------------------------------------------------------------
struct __align__(16) RecSmem {
    float hs[Bz][260];      // h, padded rows (conflict-free .128)
    float Ush[NCOL][260];   // 6 U' columns, k-contiguous
    float Psh[Bz][68];      // P [32][64] padded
    float pp[8][NCOL][Bz];  // per-warp K-split partials of h@U'
    float gsh[NCOL][Bz];    // G[t] slice (x@W')
    float ac[NCOL][Bz];     // a_cur slice
    float gt[NCOL][Bz];     // gates slice
    float Prsh[Bz];
    float biassh[NCOL];
    float s_gpp[2];
    int   s_idx;
};

__global__ __launch_bounds__(NTH, 1) void rec_kernel(
    const float* __restrict__ U, const float* __restrict__ P,
    const float* __restrict__ B_bias, const float* __restrict__ P_r,
    const float* __restrict__ U_r, const float* __restrict__ W_out,
    const float* __restrict__ b_out, float* __restrict__ out)
{
    extern __shared__ char smem_raw[];
    RecSmem& S = *reinterpret_cast<RecSmem*>(smem_raw);
    const int tid = threadIdx.x;
    const int w = tid >> 5, lane = tid & 31;
    const int bid = blockIdx.x;
    const int j0 = bid * HB;

    // ---- one-time preloads ----
    for (int i = tid; i < NCOL * Hh; i += NTH) {
        int cl = i >> 8, k = i & 255;
        int colg = (cl >> 1) * Hh + j0 + (cl & 1);
        S.Ush[cl][k] = U[(size_t)k * 1024 + colg];
    }
    for (int i = tid; i < Bz * 64; i += NTH) S.Psh[i >> 6][i & 63] = P[i];
    if (tid < Bz) S.Prsh[tid] = P_r[tid];
    if (tid < NCOL) {
        int colg = (tid >> 1) * Hh + j0 + (tid & 1);
        S.biassh[tid] = B_bias[colg];
    }
    const int mycl = w;                                    // valid for tid<192 stages
    const int mycolg = (mycl >> 1) * Hh + j0 + (mycl & 1);
    float urj = (tid < 64) ? U_r[j0 + w] : 0.f;            // w = jl for tid<64
    float c_reg = 0.f;                                     // c state for (jl=w, b=lane), tid<64
    __syncthreads();

    for (int t = 0; t < T; t++) {
        const int slot = (t - 1) & 1;   // slot published at step t-1 (t=0: both zeroed)

        // ---- A: warp0 polls all 128 slots IN PARALLEL; warps 1-2 load G[t] slice ----
        if (w == 0) {
            float ps0 = 0.f, ps1 = 0.f, ps2 = 0.f, ps3 = 0.f;
            if (t > 0) {
                unsigned pend = 0xFu;
                const uint2* a0 = &g_sync[slot][lane][0];
                const uint2* a1 = &g_sync[slot][lane + 32][0];
                const uint2* a2 = &g_sync[slot][lane + 64][0];
                const uint2* a3 = &g_sync[slot][lane + 96][0];
                do {
                    unsigned fl, pv;
                    if (pend & 1u) {
                        asm volatile("ld.acquire.gpu.global.v2.u32 {%0,%1}, [%2];"
                                     : "=r"(fl), "=r"(pv) : "l"(a0) : "memory");
                        if (fl >= (unsigned)t) { pend &= ~1u; ps0 = __uint_as_float(pv); }
                    }
                    if (pend & 2u) {
                        asm volatile("ld.acquire.gpu.global.v2.u32 {%0,%1}, [%2];"
                                     : "=r"(fl), "=r"(pv) : "l"(a1) : "memory");
                        if (fl >= (unsigned)t) { pend &= ~2u; ps1 = __uint_as_float(pv); }
                    }
                    if (pend & 4u) {
                        asm volatile("ld.acquire.gpu.global.v2.u32 {%0,%1}, [%2];"
                                     : "=r"(fl), "=r"(pv) : "l"(a2) : "memory");
                        if (fl >= (unsigned)t) { pend &= ~4u; ps2 = __uint_as_float(pv); }
                    }
                    if (pend & 8u) {
                        asm volatile("ld.acquire.gpu.global.v2.u32 {%0,%1}, [%2];"
                                     : "=r"(fl), "=r"(pv) : "l"(a3) : "memory");
                        if (fl >= (unsigned)t) { pend &= ~8u; ps3 = __uint_as_float(pv); }
                    }
                } while (pend);
            }
            float psum = (ps0 + ps1) + (ps2 + ps3);
#pragma unroll
            for (int o = 16; o; o >>= 1) psum += __shfl_xor_sync(0xffffffffu, psum, o);
            if (lane == 0) {
                float v = psum + g_xrs[t];
                float gate = 1.f / (1.f + expf(-v));
                int hi = (t - 1) > 0 ? (t - 1) : 0;
                int idx = (int)rintf((float)t * gate);
                idx = idx < 0 ? 0 : (idx > hi ? hi : idx);
                S.s_idx = idx;
            }
        } else if (tid >= 32 && tid < 80) {
            int q = tid - 32;                 // 0..47
            int cl = q >> 3, qq = q & 7;
            int colg = (cl >> 1) * Hh + j0 + (cl & 1);
            float4 v;
            const float4* gp = (const float4*)&g_G[(size_t)t * (C3 * Bz) + (size_t)colg * Bz + qq * 4];
            v.x = __ldcg((const float*)gp); v.y = __ldcg((const float*)gp + 1);
            v.z = __ldcg((const float*)gp + 2); v.w = __ldcg((const float*)gp + 3);
            *(float4*)&S.gsh[cl][qq * 4] = v;
        }
        __syncthreads();

        // ---- B: prefetch recall term; all 256 threads load h (32KB) ----
        const bool rec = (t >= OMEGA);
        const int sidx = S.s_idx;
        float bmv = 0.f;
        if (rec && tid < 192)
            bmv = __ldcg(&g_G[(size_t)sidx * (C3 * Bz) + (size_t)mycolg * Bz + lane]);
        {
            const float4* hb = (const float4*)g_pubh[slot];
#pragma unroll
            for (int r = 0; r < 8; r++) {
                int q = tid + r * NTH;
                ((float4*)&S.hs[q >> 6][0])[q & 63] = __ldcg(&hb[q]);
            }
        }
        __syncthreads();

        // ---- C: matvec h@U' (f32x2, K-split over 8 warps) ----
        {
            unsigned long long acc[NCOL] = {0ull, 0ull, 0ull, 0ull, 0ull, 0ull};
            const longlong2* hrow = (const longlong2*)&S.hs[lane][0];
#pragma unroll
            for (int q = 0; q < 8; q++) {
                longlong2 hq = hrow[w * 8 + q];
#pragma unroll
                for (int cl = 0; cl < NCOL; cl++) {
                    longlong2 uq = ((const longlong2*)&S.Ush[cl][0])[w * 8 + q];  // broadcast
                    FFMA2(acc[cl], hq.x, uq.x);
                    FFMA2(acc[cl], hq.y, uq.y);
                }
            }
#pragma unroll
            for (int cl = 0; cl < NCOL; cl++) {
                float lo, hi; UPK(acc[cl], lo, hi);
                S.pp[w][cl][lane] = lo + hi;
            }
        }
        __syncthreads();

        // ---- D: reduce partials (intra-warp handoff) + P-mix + gates ----
        if (tid < 192) {
            float s = S.gsh[mycl][lane];
#pragma unroll
            for (int ww = 0; ww < 8; ww++) s += S.pp[ww][mycl][lane];
            S.ac[mycl][lane] = s;
            __syncwarp();
            unsigned long long a1 = 0ull, a2 = 0ull;
            const longlong2* prow1 = (const longlong2*)&S.Psh[lane][0];
            const longlong2* prow2 = (const longlong2*)&S.Psh[lane][32];
            const longlong2* arow  = (const longlong2*)&S.ac[mycl][0];   // broadcast
#pragma unroll
            for (int q = 0; q < 8; q++) {
                longlong2 av = arow[q];
                longlong2 p1 = prow1[q];
                FFMA2(a1, p1.x, av.x); FFMA2(a1, p1.y, av.y);
                longlong2 p2 = prow2[q];
                FFMA2(a2, p2.x, av.x); FFMA2(a2, p2.y, av.y);
            }
            float l1, h1, l2, h2;
            UPK(a1, l1, h1); UPK(a2, l2, h2);
            float y1 = l1 + h1, y2 = l2 + h2;
            g_G[(size_t)t * (C3 * Bz) + (size_t)mycolg * Bz + lane] = y2;  // Bm[t] (block-private)
            S.gt[mycl][lane] = S.biassh[mycl] + y1 + (rec ? bmv : y2);
        }
        __syncthreads();

        // ---- E: activations, state update, publish h + {flag, partial} via release ----
        if (tid < 64) {
            float gi = S.gt[w][lane], gf = S.gt[2 + w][lane], gg = S.gt[4 + w][lane];
            float iv = 1.f / (1.f + expf(-gi));
            float fv = 1.f / (1.f + expf(-gf));
            float gv = tanhf(gg);
            c_reg = fv * c_reg + iv * gv;
            float h = iv * tanhf(c_reg);   // o_t = i_t (faithful to source)
            g_pubh[t & 1][lane * Hh + j0 + w] = h;
            if (t == T - 1) g_hfin[lane * Hh + j0 + w] = h;
            float v = S.Prsh[lane] * h * urj;
#pragma unroll
            for (int o = 16; o; o >>= 1) v += __shfl_xor_sync(0xffffffffu, v, o);
            if (lane == 0) S.s_gpp[w] = v;
            asm volatile("bar.sync 1, 64;");
            if (tid == 0) {
                float p = S.s_gpp[0] + S.s_gpp[1];
                asm volatile("st.release.gpu.global.v2.u32 [%0], {%1,%2};"
                             :: "l"(&g_sync[t & 1][bid][0]),
                                "r"((unsigned)(t + 1)), "r"(__float_as_uint(p))
                             : "memory");
            }
        }
        // no trailing sync: next A's __syncthreads orders shared-memory reuse
    }

    // ---- final: out = h_final @ W_out + b_out (block 0) ----
    if (bid == 0) {
        if (tid < NB) {
            const uint2* ap = &g_sync[(T - 1) & 1][tid][0];
            unsigned fl, pv;
            do {
                asm volatile("ld.acquire.gpu.global.v2.u32 {%0,%1}, [%2];"
                             : "=r"(fl), "=r"(pv) : "l"(ap) : "memory");
            } while (fl < (unsigned)T);
        }
        __syncthreads();
        int b = tid >> 3, ks = tid & 7;
        const float4* hr4 = (const float4*)(g_hfin + b * Hh);
        const float4* wo4 = (const float4*)W_out;
        float s = 0.f;
#pragma unroll
        for (int q = 0; q < 8; q++) {
            float4 hv = __ldcg(&hr4[ks * 8 + q]);
            float4 wv = wo4[ks * 8 + q];
            s += hv.x * wv.x + hv.y * wv.y + hv.z * wv.z + hv.w * wv.w;
        }
        s += __shfl_xor_sync(0xffffffffu, s, 1);
        s += __shfl_xor_sync(0xffffffffu, s, 2);
        s += __shfl_xor_sync(0xffffffffu, s, 4);
        if (ks == 0) out[b] = s + b_out[0];
    }
}

// ------------------------------------------------------------------
extern "C" void kernel_launch(void* const* d_in, const int* in_sizes, int n_in,
                              void* d_out, int out_size) {
    const float* x      = (const float*)d_in[0];   // [32,1024,256]
    const float* W      = (const float*)d_in[1];   // [256,1024]
    const float* U      = (const float*)d_in[2];   // [256,1024]
    const float* P      = (const float*)d_in[3];   // [32,64]
    const float* B_bias = (const float*)d_in[4];   // [1024]
    const float* W_r    = (const float*)d_in[5];   // [256,1]
    const float* P_r    = (const float*)d_in[6];   // [1,32]
    const float* U_r    = (const float*)d_in[7];   // [256,1]
    const float* W_out  = (const float*)d_in[8];   // [256,1]
    const float* b_out  = (const float*)d_in[9];   // [1]
    float* out = (float*)d_out;                    // [32,1]

    (void)in_sizes; (void)n_in; (void)out_size;

    init_kernel<<<1, NTH>>>();
    xr_kernel<<<T, 256>>>(x, W_r, P_r);
    gemm_kernel<<<dim3(12, T), 256>>>(x, W);

    cudaFuncSetAttribute(rec_kernel, cudaFuncAttributeMaxDynamicSharedMemorySize,
                         (int)sizeof(RecSmem));
    rec_kernel<<<NB, NTH, sizeof(RecSmem)>>>(U, P, B_bias, P_r, U_r, W_out, b_out, out);
}